// round 16
// baseline (speedup 1.0000x reference)
#include <cuda_runtime.h>
#include <cuda_bf16.h>
#include <math_constants.h>
#include <cstdint>

// Problem constants
#define D        512
#define KCODES   1024
#define NMAX     16384
#define MARGIN   4e-3f      // int8 screen: ~12 sigma of screen-score error

// ---------------------------------------------------------------------------
// Scratch (device globals; no cudaMalloc allowed)
// ---------------------------------------------------------------------------
__device__ float  g_eSq[KCODES];
__device__ float  g_xSq[NMAX];
__device__ float  g_se[KCODES];     // per-code int8 scale
__device__ float  g_sx[NMAX];       // per-row int8 scale
__device__ double g_acc;
__device__ __align__(16) int8_t        g_Ei8[(size_t)KCODES * D];     // 512 KB
__device__ __align__(16) int8_t        g_Xi8[(size_t)NMAX * D];       // 8 MB
__device__ __align__(16) __nv_bfloat16 g_scoresh[(size_t)NMAX * KCODES]; // 32 MB

// ---------------------------------------------------------------------------
// PTX wrappers (base-target instructions only: ldmatrix / mma.sync / cp.async)
// ---------------------------------------------------------------------------
__device__ __forceinline__ uint32_t smem_u32(const void* p) {
    uint32_t a;
    asm("{ .reg .u64 t; cvta.to.shared.u64 t, %1; cvt.u32.u64 %0, t; }"
        : "=r"(a) : "l"(p));
    return a;
}
__device__ __forceinline__ void ldmatrix_x4(uint32_t r[4], uint32_t addr) {
    asm volatile("ldmatrix.sync.aligned.m8n8.x4.shared.b16 {%0,%1,%2,%3}, [%4];"
                 : "=r"(r[0]), "=r"(r[1]), "=r"(r[2]), "=r"(r[3]) : "r"(addr));
}
__device__ __forceinline__ void ldmatrix_x2(uint32_t r[2], uint32_t addr) {
    asm volatile("ldmatrix.sync.aligned.m8n8.x2.shared.b16 {%0,%1}, [%2];"
                 : "=r"(r[0]), "=r"(r[1]) : "r"(addr));
}
// int8 MMA: D(s32) += A(s8,16x32) * B(s8,32x8)
__device__ __forceinline__ void mma_s8(int d[4], const uint32_t a[4],
                                       const uint32_t b[2]) {
    asm volatile(
        "mma.sync.aligned.m16n8k32.row.col.s32.s8.s8.s32 "
        "{%0,%1,%2,%3}, {%4,%5,%6,%7}, {%8,%9}, {%0,%1,%2,%3};"
        : "+r"(d[0]), "+r"(d[1]), "+r"(d[2]), "+r"(d[3])
        : "r"(a[0]), "r"(a[1]), "r"(a[2]), "r"(a[3]), "r"(b[0]), "r"(b[1]));
}
#define CP_ASYNC16(dst, src) \
    asm volatile("cp.async.cg.shared.global [%0], [%1], 16;" \
                 :: "r"(dst), "l"(src) : "memory")
#define CP_COMMIT() asm volatile("cp.async.commit_group;" ::: "memory")
#define CP_WAIT(n)  asm volatile("cp.async.wait_group %0;" :: "n"(n) : "memory")

__device__ __forceinline__ uint32_t pack4(float a, float b, float c, float d2,
                                          float inv) {
    int q0 = max(-127, min(127, __float2int_rn(a * inv)));
    int q1 = max(-127, min(127, __float2int_rn(b * inv)));
    int q2 = max(-127, min(127, __float2int_rn(c * inv)));
    int q3 = max(-127, min(127, __float2int_rn(d2 * inv)));
    return (uint32_t)(q0 & 0xff) | ((uint32_t)(q1 & 0xff) << 8) |
           ((uint32_t)(q2 & 0xff) << 16) | ((uint32_t)(q3 & 0xff) << 24);
}

// ---------------------------------------------------------------------------
// Kernel 0: zero the loss accumulator
// ---------------------------------------------------------------------------
__global__ void zero_kernel() { g_acc = 0.0; }

// ---------------------------------------------------------------------------
// Kernel 1: eSq[k], per-code int8 scale + quantized codebook (all fused)
// ---------------------------------------------------------------------------
__global__ void esq_kernel(const float* __restrict__ E) {
    int c = blockIdx.x;
    const float4* row = reinterpret_cast<const float4*>(E + (size_t)c * D);
    int t = threadIdx.x;
    float4 v = row[t];

    float s  = v.x * v.x + v.y * v.y + v.z * v.z + v.w * v.w;
    float mx = fmaxf(fmaxf(fabsf(v.x), fabsf(v.y)), fmaxf(fabsf(v.z), fabsf(v.w)));
    #pragma unroll
    for (int off = 16; off > 0; off >>= 1) {
        s  += __shfl_xor_sync(0xFFFFFFFFu, s, off);
        mx = fmaxf(mx, __shfl_xor_sync(0xFFFFFFFFu, mx, off));
    }
    __shared__ float ws[4], wm[4];
    if ((t & 31) == 0) { ws[t >> 5] = s; wm[t >> 5] = mx; }
    __syncthreads();
    float sum  = ws[0] + ws[1] + ws[2] + ws[3];
    float maxv = fmaxf(fmaxf(wm[0], wm[1]), fmaxf(wm[2], wm[3]));
    maxv = fmaxf(maxv, 1e-20f);
    float inv = 127.0f / maxv;

    *reinterpret_cast<uint32_t*>(&g_Ei8[(size_t)c * D + t * 4]) =
        pack4(v.x, v.y, v.z, v.w, inv);
    if (t == 0) { g_eSq[c] = sum; g_se[c] = maxv / 127.0f; }
}

// ---------------------------------------------------------------------------
// Kernel 1b: strict-sequential xSq (reference rounding) + per-row int8
// scale + quantized X (fused; the row is already in smem)
// ---------------------------------------------------------------------------
__global__ void xsq_kernel(const float* __restrict__ X) {
    __shared__ float buf[8][512];
    int w    = threadIdx.x >> 5;
    int lane = threadIdx.x & 31;
    int row  = blockIdx.x * 8 + w;
    const float4* src = reinterpret_cast<const float4*>(X + (size_t)row * D);
    #pragma unroll
    for (int i = 0; i < 4; i++) {
        float4 v = src[lane + 32 * i];
        *reinterpret_cast<float4*>(&buf[w][(lane + 32 * i) * 4]) = v;
    }
    __syncwarp();

    // per-row max (all lanes), then quantize 16 contiguous elements per lane
    float mx = 0.0f;
    #pragma unroll
    for (int i = 0; i < 16; i++) mx = fmaxf(mx, fabsf(buf[w][lane * 16 + i]));
    #pragma unroll
    for (int off = 16; off > 0; off >>= 1)
        mx = fmaxf(mx, __shfl_xor_sync(0xFFFFFFFFu, mx, off));
    mx = fmaxf(mx, 1e-20f);
    float inv = 127.0f / mx;
    #pragma unroll
    for (int g = 0; g < 4; g++) {
        const float* p = &buf[w][lane * 16 + g * 4];
        *reinterpret_cast<uint32_t*>(&g_Xi8[(size_t)row * D + lane * 16 + g * 4]) =
            pack4(p[0], p[1], p[2], p[3], inv);
    }

    if (lane == 0) {
        g_sx[row] = mx / 127.0f;
        float s = 0.0f;
        #pragma unroll 16
        for (int i = 0; i < 512; i++) {
            float x = buf[w][i];
            s = __fadd_rn(s, __fmul_rn(x, x));
        }
        g_xSq[row] = s;
    }
}

// ---------------------------------------------------------------------------
// Kernel 2: SCREEN — int8 mma.sync GEMM, s = esq - 2*sx*se*idot, bf16 scores.
// 128 CTAs x 256 threads. A (128x512 int8) persistent in smem; B streamed via
// 4-stage cp.async (stage = 128 codes x 128 K-bytes). 32 steps: nt=s>>2,
// c=s&3. ldmatrix.b16 on int8 (1 b16 unit = 2 int8 along K): fragments match
// the s8 k32 mma layout exactly (same address pattern as the proven bf16 code,
// strides in bytes).
// ---------------------------------------------------------------------------
#define A_STRIDE_B 528        // bytes/row: 33x16B, odd -> conflict-free ldmatrix
#define B_STRIDE_B 144        // bytes/row: 9x16B, odd
#define NSTAGE     4
#define BSTG_BYTES (128 * B_STRIDE_B)                     // 18432
#define SM_A_BYTES (128 * A_STRIDE_B)                     // 67584
#define SM_B_OFF   SM_A_BYTES
#define SM_ESQ_OFF (SM_B_OFF + NSTAGE * BSTG_BYTES)       // 141312
#define SM_SE_OFF  (SM_ESQ_OFF + 4096)                    // 145408
#define SM_SX_OFF  (SM_SE_OFF + 4096)                     // 149504
#define SM_SCR_TOTAL (SM_SX_OFF + 512)                    // 150016

__global__ __launch_bounds__(256, 1)
void screen_kernel() {
    extern __shared__ char sm[];
    float* esm  = reinterpret_cast<float*>(sm + SM_ESQ_OFF);
    float* sesm = reinterpret_cast<float*>(sm + SM_SE_OFF);
    float* sxsm = reinterpret_cast<float*>(sm + SM_SX_OFF);

    const int tid  = threadIdx.x;
    const int lane = tid & 31;
    const int wid  = tid >> 5;
    const int wm   = wid >> 2;          // 0..1 (64-row group)
    const int wn   = wid & 3;           // 0..3 (32-code group)
    const int rowBase = blockIdx.x * 128;

    const uint32_t sA = smem_u32(sm);
    const uint32_t sB = sA + SM_B_OFF;

    // cp.async issue for pipeline step s: stage = 128 codes x 128 bytes
    const int ldR = tid >> 1;           // 0..127 (code row)
    const int ldH = (tid & 1) * 64;     // 64-byte half
    auto issue = [&](int s) {
        if (s < 32) {
            int nt = s >> 2, c = s & 3;
            const int8_t* src = g_Ei8 + (size_t)(nt * 128 + ldR) * D + c * 128 + ldH;
            uint32_t dst = sB + (uint32_t)((s & (NSTAGE - 1)) * BSTG_BYTES)
                              + (uint32_t)(ldR * B_STRIDE_B + ldH);
            #pragma unroll
            for (int l = 0; l < 4; l++)
                CP_ASYNC16(dst + l * 16, src + l * 16);
        }
        CP_COMMIT();
    };

    issue(0); issue(1); issue(2);

    // A: X int8 rows -> smem (plain 16B copies, off critical path)
    #pragma unroll 4
    for (int i = 0; i < 16; i++) {
        int f  = tid + i * 256;         // 16B-chunk id (4096 total = 128x32)
        int r  = f >> 5;
        int ck = (f & 31) * 16;
        *reinterpret_cast<uint4*>(sm + r * A_STRIDE_B + ck) =
            *reinterpret_cast<const uint4*>(&g_Xi8[(size_t)(rowBase + r) * D + ck]);
    }
    for (int i = tid; i < KCODES; i += 256) { esm[i] = g_eSq[i]; sesm[i] = g_se[i]; }
    if (tid < 128) sxsm[tid] = g_sx[rowBase + tid];
    __syncthreads();

    // ldmatrix lane address components (byte units)
    const int aRowLane = ((lane >> 3) & 1) * 8 + (lane & 7);
    const int aKByte   = ((lane >> 4) & 1) * 16;
    const int bRowLane = lane & 7;
    const int bKByte   = ((lane >> 3) & 1) * 16;

    int acc[4][4][4];
    #pragma unroll
    for (int mi = 0; mi < 4; mi++)
        #pragma unroll
        for (int ni = 0; ni < 4; ni++)
            #pragma unroll
            for (int q = 0; q < 4; q++) acc[mi][ni][q] = 0;

    for (int s = 0; s < 32; s++) {
        const int nt = s >> 2, c = s & 3;
        CP_WAIT(NSTAGE - 2);
        __syncthreads();
        issue(s + NSTAGE - 1);

        const uint32_t bufB = sB + (uint32_t)((s & (NSTAGE - 1)) * BSTG_BYTES);
        #pragma unroll
        for (int ks = 0; ks < 4; ks++) {      // k32 steps within 128-byte chunk
            uint32_t afr[4][4];
            const int kByte = c * 128 + ks * 32 + aKByte;
            #pragma unroll
            for (int mi = 0; mi < 4; mi++) {
                int r = wm * 64 + mi * 16 + aRowLane;
                ldmatrix_x4(afr[mi], sA + (uint32_t)(r * A_STRIDE_B + kByte));
            }
            uint32_t bfr[4][2];
            const int kb = ks * 32 + bKByte;
            #pragma unroll
            for (int ni = 0; ni < 4; ni++) {
                int r = wn * 32 + ni * 8 + bRowLane;
                ldmatrix_x2(bfr[ni], bufB + (uint32_t)(r * B_STRIDE_B + kb));
            }
            #pragma unroll
            for (int mi = 0; mi < 4; mi++)
                #pragma unroll
                for (int ni = 0; ni < 4; ni++)
                    mma_s8(acc[mi][ni], afr[mi], bfr[ni]);
        }

        if (c == 3) {
            // epilogue for tile nt: dequant + score -> bf16 matrix
            const int nbase = nt * 128;
            #pragma unroll
            for (int mi = 0; mi < 4; mi++) {
                int rloc = wm * 64 + mi * 16 + (lane >> 2);
                int r0 = rowBase + rloc;
                float tsx0 = 2.0f * sxsm[rloc];
                float tsx1 = 2.0f * sxsm[rloc + 8];
                #pragma unroll
                for (int ni = 0; ni < 4; ni++) {
                    int col = nbase + wn * 32 + ni * 8 + (lane & 3) * 2;
                    float es0 = esm[col], es1 = esm[col + 1];
                    float se0 = sesm[col], se1 = sesm[col + 1];
                    __nv_bfloat162 lo = __floats2bfloat162_rn(
                        es0 - tsx0 * se0 * (float)acc[mi][ni][0],
                        es1 - tsx0 * se1 * (float)acc[mi][ni][1]);
                    __nv_bfloat162 hi = __floats2bfloat162_rn(
                        es0 - tsx1 * se0 * (float)acc[mi][ni][2],
                        es1 - tsx1 * se1 * (float)acc[mi][ni][3]);
                    *reinterpret_cast<__nv_bfloat162*>(
                        &g_scoresh[(size_t)r0 * KCODES + col]) = lo;
                    *reinterpret_cast<__nv_bfloat162*>(
                        &g_scoresh[(size_t)(r0 + 8) * KCODES + col]) = hi;
                    acc[mi][ni][0] = 0; acc[mi][ni][1] = 0;
                    acc[mi][ni][2] = 0; acc[mi][ni][3] = 0;
                }
            }
        }
    }
}

// ---------------------------------------------------------------------------
// Kernel 3: SELECT + EXACT + GATHER + LOSS.  One block (128 thr) per row.
// candidates = { s < min + MARGIN } (superset: screen err << MARGIN), then
// exact fp32 quantized score fl((xsq+esq)-fl(2*dot)) with first-index
// tie-break == reference.
// ---------------------------------------------------------------------------
#define MAXCAND 32
__global__ __launch_bounds__(128)
void select_kernel(const float* __restrict__ X, const float* __restrict__ E,
                   float* __restrict__ outQ, float* __restrict__ outIdx) {
    const int row  = blockIdx.x;
    const int t    = threadIdx.x;
    const int lane = t & 31;
    const int wid  = t >> 5;

    __shared__ float xrow[512];
    __shared__ float wred[4];
    __shared__ int   cand[MAXCAND];
    __shared__ float cval[MAXCAND];
    __shared__ int   ccnt;
    __shared__ int   bestIdx_s;
    __shared__ float fbV[128];
    __shared__ int   fbI[128];

    float4 xv = reinterpret_cast<const float4*>(X + (size_t)row * D)[t];
    *reinterpret_cast<float4*>(&xrow[t * 4]) = xv;
    if (t == 0) ccnt = 0;

    const __nv_bfloat16* srow = g_scoresh + (size_t)row * KCODES;
    uint4 raw = reinterpret_cast<const uint4*>(srow)[t];
    float sv[8];
    {
        __nv_bfloat162 h0 = *reinterpret_cast<__nv_bfloat162*>(&raw.x);
        __nv_bfloat162 h1 = *reinterpret_cast<__nv_bfloat162*>(&raw.y);
        __nv_bfloat162 h2 = *reinterpret_cast<__nv_bfloat162*>(&raw.z);
        __nv_bfloat162 h3 = *reinterpret_cast<__nv_bfloat162*>(&raw.w);
        sv[0] = __bfloat162float(h0.x); sv[1] = __bfloat162float(h0.y);
        sv[2] = __bfloat162float(h1.x); sv[3] = __bfloat162float(h1.y);
        sv[4] = __bfloat162float(h2.x); sv[5] = __bfloat162float(h2.y);
        sv[6] = __bfloat162float(h3.x); sv[7] = __bfloat162float(h3.y);
    }
    float m = sv[0];
    #pragma unroll
    for (int j = 1; j < 8; j++) m = fminf(m, sv[j]);
    #pragma unroll
    for (int off = 16; off > 0; off >>= 1)
        m = fminf(m, __shfl_xor_sync(0xFFFFFFFFu, m, off));
    if (lane == 0) wred[wid] = m;
    __syncthreads();
    m = fminf(fminf(wred[0], wred[1]), fminf(wred[2], wred[3]));
    const float thresh = m + MARGIN;

    #pragma unroll
    for (int j = 0; j < 8; j++) {
        if (sv[j] < thresh) {
            int slot = atomicAdd(&ccnt, 1);
            if (slot < MAXCAND) cand[slot] = t * 8 + j;
        }
    }
    __syncthreads();
    int cnt = ccnt;
    const float xs = g_xSq[row];

    if (cnt <= MAXCAND) {
        for (int i = wid; i < cnt; i += 4) {
            int code = cand[i];
            const float* e = E + (size_t)code * D;
            float p = 0.0f;
            #pragma unroll 4
            for (int j = lane; j < D; j += 32) p = fmaf(xrow[j], e[j], p);
            #pragma unroll
            for (int off = 16; off > 0; off >>= 1)
                p += __shfl_xor_sync(0xFFFFFFFFu, p, off);
            if (lane == 0)
                cval[i] = __fsub_rn(__fadd_rn(xs, g_eSq[code]),
                                    __fmul_rn(2.0f, p));
        }
        __syncthreads();
        if (t == 0) {
            float bv = CUDART_INF_F; int bi = 0x7fffffff;
            for (int i = 0; i < cnt; i++) {
                float v = cval[i]; int ix = cand[i];
                if (v < bv || (v == bv && ix < bi)) { bv = v; bi = ix; }
            }
            bestIdx_s = bi;
        }
    } else {
        float bv = CUDART_INF_F; int bi = 0x7fffffff;
        for (int j = 0; j < 8; j++) {
            int code = t * 8 + j;
            const float* e = E + (size_t)code * D;
            float p = 0.0f;
            for (int k = 0; k < D; k++) p = fmaf(xrow[k], e[k], p);
            float v = __fsub_rn(__fadd_rn(xs, g_eSq[code]), __fmul_rn(2.0f, p));
            if (v < bv || (v == bv && code < bi)) { bv = v; bi = code; }
        }
        fbV[t] = bv; fbI[t] = bi;
        __syncthreads();
        if (t == 0) {
            for (int i = 1; i < 128; i++) {
                if (fbV[i] < bv || (fbV[i] == bv && fbI[i] < bi)) {
                    bv = fbV[i]; bi = fbI[i];
                }
            }
            bestIdx_s = bi;
        }
    }
    __syncthreads();
    const int bi = bestIdx_s;

    // gather + loss (outQ only 4B-aligned -> scalar stores, coalesced)
    float4 ev = reinterpret_cast<const float4*>(E + (size_t)bi * D)[t];
    float* q = outQ + (size_t)row * D;
    q[t * 4 + 0] = ev.x; q[t * 4 + 1] = ev.y;
    q[t * 4 + 2] = ev.z; q[t * 4 + 3] = ev.w;
    float dx = ev.x - xv.x, dy = ev.y - xv.y, dz = ev.z - xv.z, dw = ev.w - xv.w;
    float s = dx * dx + dy * dy + dz * dz + dw * dw;
    #pragma unroll
    for (int off = 16; off > 0; off >>= 1)
        s += __shfl_down_sync(0xFFFFFFFFu, s, off);
    if (lane == 0) wred[wid] = s;
    __syncthreads();
    if (t == 0) {
        atomicAdd(&g_acc, (double)(wred[0] + wred[1] + wred[2] + wred[3]));
        outIdx[row] = (float)bi;
    }
}

// ---------------------------------------------------------------------------
// Kernel 4: finalize loss = 1.25 * mean((q-x)^2)
// ---------------------------------------------------------------------------
__global__ void finalize_kernel(float* __restrict__ outLoss, int n) {
    outLoss[0] = (float)(1.25 * g_acc / ((double)n * (double)D));
}

// ---------------------------------------------------------------------------
extern "C" void kernel_launch(void* const* d_in, const int* in_sizes, int n_in,
                              void* d_out, int out_size) {
    const float* X = (const float*)d_in[0];   // [N, 512]
    const float* E = (const float*)d_in[1];   // [1024, 512]

    const int N = in_sizes[0] / D;            // 16384

    float* out      = (float*)d_out;
    float* outLoss  = out;
    float* outQ     = out + 1;
    float* outIdx   = out + 1 + (size_t)N * D;

    cudaFuncSetAttribute(screen_kernel,
                         cudaFuncAttributeMaxDynamicSharedMemorySize, SM_SCR_TOTAL);

    zero_kernel<<<1, 1>>>();
    esq_kernel<<<KCODES, 128>>>(E);
    xsq_kernel<<<N / 8, 256>>>(X);
    screen_kernel<<<N / 128, 256, SM_SCR_TOTAL>>>();
    select_kernel<<<N, 128>>>(X, E, outQ, outIdx);
    finalize_kernel<<<1, 1>>>(outLoss, N);
}